// round 10
// baseline (speedup 1.0000x reference)
#include <cuda_runtime.h>
#include <cstdint>

// ============================================================================
// CgpHmmCell: HMM forward scan. B=128, T=8192, S=512, M=64.
//
// Linear-domain rescaled recurrence (exactly the reference math):
//   F_0[b][s] = (s==0) ? E_0[b][0]+eps : 0 ;  C_0 = 0
//   step t:    M = max_s F_{t-1}[b][s] ;  C += log(M)  (Kahan)
//              y[b][j]   = sum_s F_{t-1}[b][s] * A[s][j]
//              F_t[b][j] = (E_t[b][j]+eps) * (y * (1/M) + eps)
//   alpha_T = log(F_T) + C ;  loglik = log(sum F_T/M_T + S*eps) + log(M_T) + C
//
// 16 teams x 8-CTA clusters, 1024 threads/CTA. A slice repacked j-pair-major
// in smem; packed f32x2 MAC; warp-replicated invM; register-resident Kahan C;
// one bar.sync + one cluster.sync per step.
// ============================================================================

#define T_LEN 8192
#define EPS   1e-16f

typedef unsigned long long ull;

// word-offset smem map
#define FSTR      516                  // F batch stride (even, bank-spread)
#define FBUFW     4128                 // 8 * FSTR
#define OFF_FB    32768                // fb[2][8][FSTR]
#define OFF_PART  41024                // part[256 rows][17 ull]
#define OFF_MAXB  49728                // maxb[2][8 b][8 src]
#define OFF_CV    49856                // cv[8]
#define SMEM_WORDS 49872
#define SMEM_BYTES (SMEM_WORDS * 4)    // 199488

__device__ unsigned char g_sym[128 * T_LEN];

// ---------------------------------------------------------------------------
__global__ void sym_kernel(const float* __restrict__ x) {
    int gw   = (blockIdx.x * blockDim.x + threadIdx.x) >> 5;
    int lane = threadIdx.x & 31;
    if (gw >= 128 * T_LEN) return;
    const float* p = x + (size_t)gw * 64;
    unsigned m1 = __ballot_sync(0xffffffffu, p[lane] > 0.5f);
    unsigned m2 = __ballot_sync(0xffffffffu, p[lane + 32] > 0.5f);
    if (lane == 0)
        g_sym[gw] = (unsigned char)(m1 ? (__ffs(m1) - 1) : (31 + __ffs(m2)));
}

// ---------------------------------------------------------------------------
__device__ __forceinline__ uint32_t smem_u32(const void* p) {
    uint32_t a;
    asm("{ .reg .u64 t; cvta.to.shared.u64 t, %1; cvt.u32.u64 %0, t; }"
        : "=r"(a) : "l"(p));
    return a;
}
__device__ __forceinline__ uint32_t mapa_u32(uint32_t a, uint32_t r) {
    uint32_t o;
    asm("mapa.shared::cluster.u32 %0, %1, %2;" : "=r"(o) : "r"(a), "r"(r));
    return o;
}
__device__ __forceinline__ void stc_f32(uint32_t a, float v) {
    asm volatile("st.shared::cluster.f32 [%0], %1;" :: "r"(a), "f"(v) : "memory");
}
__device__ __forceinline__ void stc_b64(uint32_t a, ull v) {
    asm volatile("st.shared::cluster.b64 [%0], %1;" :: "r"(a), "l"(v) : "memory");
}
__device__ __forceinline__ void cluster_arrive() {
    asm volatile("barrier.cluster.arrive.aligned;" ::: "memory");
}
__device__ __forceinline__ void cluster_wait() {
    asm volatile("barrier.cluster.wait.aligned;" ::: "memory");
}
#define FMA2(d, a, b) \
    asm("fma.rn.f32x2 %0, %1, %2, %0;" : "+l"(d) : "l"(a), "l"(b))
#define ADD2(d, a, b) \
    asm("add.rn.f32x2 %0, %1, %2;" : "=l"(d) : "l"(a), "l"(b))
#define MUL2(d, a, b) \
    asm("mul.rn.f32x2 %0, %1, %2;" : "=l"(d) : "l"(a), "l"(b))
#define DUP2(d, f) \
    asm("mov.b64 %0, {%1, %1};" : "=l"(d) : "f"(f))
#define PACK2(d, lo, hi) \
    asm("mov.b64 %0, {%1, %2};" : "=l"(d) : "f"(lo), "f"(hi))
#define UNPACK2(lo, hi, s) \
    asm("mov.b64 {%0, %1}, %2;" : "=f"(lo), "=f"(hi) : "l"(s))

// ---------------------------------------------------------------------------
__global__ void __launch_bounds__(1024, 1) __cluster_dims__(8, 1, 1)
hmm_kernel(const float* __restrict__ A, const float* __restrict__ Bm,
           float* __restrict__ out, int out_size) {
    extern __shared__ float sm[];
    float* fb   = sm + OFF_FB;
    ull*   part = (ull*)(sm + OFF_PART);
    float* maxb = sm + OFF_MAXB;
    float* cvs  = sm + OFF_CV;

    int tid = threadIdx.x;
    uint32_t rank;
    asm("mov.u32 %0, %%cluster_ctarank;" : "=r"(rank));
    int team = blockIdx.x >> 3;
    int w = tid >> 5, lane = tid & 31;
    int bp = w & 3, jq = w >> 2;           // MAC identity: batches {2bp,2bp+1}, j-oct jq

    // ---- init: repack A slice as At2[jp][512] ull (j-pair-major transpose) ----
    for (int i = tid; i < 512 * 64; i += 1024) {
        int s = i >> 6, j = i & 63;
        float v = A[s * 512 + (rank << 6) + j];
        sm[(((j >> 1) << 9) + s) * 2 + (j & 1)] = v;
    }
    // ---- init F buffer 0, maxb ----
    for (int i = tid; i < FBUFW; i += 1024) fb[i] = 0.0f;
    for (int i = tid; i < 128; i += 1024) maxb[i] = 0.0f;
    __syncthreads();
    if (tid < 8) {
        int bglob = team * 8 + tid;
        float e0 = Bm[(int)g_sym[(size_t)bglob * T_LEN] * 512] + EPS;
        fb[tid * FSTR] = e0;               // F0[b][0]
        maxb[tid * 8] = e0;                // parity0, src0
    }
    __syncthreads();
    cluster_arrive(); cluster_wait();      // peers ready before t=1 pushes

    // peer smem bases
    uint32_t base = smem_u32(sm);
    uint32_t pb[8];
    #pragma unroll
    for (int c = 0; c < 8; ++c) pb[c] = mapa_u32(base, c);

    // Kahan C in registers (warps 0-3, lanes 0-1: batch = 2*w + lane)
    float Cv = 0.0f, Ck = 0.0f;

    // finalize identity (tid<256): warp fw 0..7 -> batch fbat, jp = lane
    int fbat = 2 * (w & 3) + (w >> 2);     // valid for w<8
    const unsigned char* fsym = g_sym + (size_t)(team * 8 + fbat) * T_LEN;
    const float* fE = Bm + (rank << 6) + (lane << 1);
    uint32_t fpush_base = (uint32_t)(OFF_FB + fbat * FSTR + (rank << 6) + (lane << 1)) << 2;
    uint32_t mpush_base = (uint32_t)(OFF_MAXB + fbat * 8 + rank) << 2;

    const ull* Ab = ((const ull*)sm) + ((jq << 2) << 9) + lane;
    ull EPS2; { float e = EPS; DUP2(EPS2, e); }

    for (int t = 1; t < T_LEN; ++t) {
        int p = t & 1, rp = p ^ 1;

        // ---- per-warp invM for this warp's 2 batches (broadcast reads) ----
        float M0, M1;
        {
            const float* mr0 = maxb + rp * 64 + (bp << 4);       // b=2bp row
            const float* mr1 = mr0 + 8;
            M0 = mr0[0]; M1 = mr1[0];
            #pragma unroll
            for (int c = 1; c < 8; ++c) {
                M0 = fmaxf(M0, mr0[c]); M1 = fmaxf(M1, mr1[c]);
            }
        }
        float inv0 = 1.0f / M0, inv1 = 1.0f / M1;

        // ---- Kahan C (off critical path; warps 0-3 lanes 0-1) ----
        if (w < 4 && lane < 2) {
            float M = lane ? M1 : M0;
            float yv = logf(M) - Ck;
            float tt = Cv + yv;
            Ck = (tt - Cv) - yv;
            Cv = tt;
        }

        // ---- E prefetch (finalize threads) ----
        float2 e2;
        if (tid < 256) e2 = *(const float2*)(fE + (int)fsym[t] * 512);

        // ---- MAC: acc[2][4] f32x2 over this thread's 16 s values ----
        const float* Fr = fb + rp * FBUFW + (bp << 1) * FSTR + lane;
        ull acc00 = 0, acc01 = 0, acc02 = 0, acc03 = 0;
        ull acc10 = 0, acc11 = 0, acc12 = 0, acc13 = 0;
        #pragma unroll
        for (int k = 0; k < 16; ++k) {
            int so = k << 5;
            float f0 = Fr[so], f1 = Fr[so + FSTR];
            ull a0 = Ab[so], a1 = Ab[so + 512], a2 = Ab[so + 1024], a3 = Ab[so + 1536];
            ull d0, d1; DUP2(d0, f0); DUP2(d1, f1);
            FMA2(acc00, a0, d0); FMA2(acc01, a1, d0);
            FMA2(acc02, a2, d0); FMA2(acc03, a3, d0);
            FMA2(acc10, a0, d1); FMA2(acc11, a1, d1);
            FMA2(acc12, a2, d1); FMA2(acc13, a3, d1);
        }

        // ---- xor16 pre-reduce + stage 16-wide partials ----
        {
            ull* pr = part + ((bp << 1) * 32 + (jq << 2)) * 17 + lane;  // row(b=2bp, jp=jq*4)
            ull v, o;
            #pragma unroll
            for (int q = 0; q < 8; ++q) {
                switch (q) {
                    case 0: v = acc00; break; case 1: v = acc01; break;
                    case 2: v = acc02; break; case 3: v = acc03; break;
                    case 4: v = acc10; break; case 5: v = acc11; break;
                    case 6: v = acc12; break; default: v = acc13; break;
                }
                o = __shfl_xor_sync(0xffffffffu, v, 16);
                ADD2(v, v, o);
                int bi = q >> 2, ji = q & 3;
                if (lane < 16) pr[(bi * 32 + ji) * 17] = v;
            }
        }
        __syncthreads();

        // ---- finalize + push (tid < 256) ----
        if (tid < 256) {
            const ull* pr = part + (fbat * 32 + lane) * 17;
            ull y2 = pr[0];
            #pragma unroll
            for (int k = 1; k < 16; ++k) { ull q = pr[k]; ADD2(y2, y2, q); }

            float invF = (w >> 2) ? inv1 : inv0;
            ull iv; DUP2(iv, invF);
            ull t1 = EPS2;
            FMA2(t1, y2, iv);
            ull e2p; PACK2(e2p, e2.x + EPS, e2.y + EPS);
            ull f2; MUL2(f2, e2p, t1);

            uint32_t off = fpush_base + ((uint32_t)(p * FBUFW) << 2);
            #pragma unroll
            for (int c = 0; c < 8; ++c) stc_b64(pb[c] + off, f2);

            // per-(CTA,b) max
            float lo, hi; UNPACK2(lo, hi, f2);
            float m = fmaxf(lo, hi);
            #pragma unroll
            for (int o2 = 16; o2; o2 >>= 1)
                m = fmaxf(m, __shfl_xor_sync(0xffffffffu, m, o2));
            if (lane == 0) {
                uint32_t moff = mpush_base + ((uint32_t)(p * 64) << 2);
                #pragma unroll
                for (int c = 0; c < 8; ++c) stc_f32(pb[c] + moff, m);
            }
        }
        cluster_arrive();
        cluster_wait();
    }

    // ---- epilogue ----
    if (w < 4 && lane < 2) cvs[2 * w + lane] = Cv;
    __syncthreads();

    if (tid < 512) {
        int b = tid >> 6, oj = tid & 63;
        float F = fb[FBUFW + b * FSTR + (rank << 6) + oj];   // final parity = 1
        float alpha = logf(F) + cvs[b];
        if (out_size >= 65536)
            out[(size_t)(team * 8 + b) * 512 + (rank << 6) + oj] = alpha;
    }

    if (rank == 0 && w < 8) {
        int b = w;
        const float* fr = fb + FBUFW + b * FSTR;
        float sum = 0.0f;
        for (int s = lane; s < 512; s += 32) sum += fr[s];
        #pragma unroll
        for (int o2 = 16; o2; o2 >>= 1)
            sum += __shfl_xor_sync(0xffffffffu, sum, o2);
        if (lane == 0) {
            const float* mr = maxb + 64 + b * 8;
            float M = mr[0];
            #pragma unroll
            for (int c = 1; c < 8; ++c) M = fmaxf(M, mr[c]);
            float ll = logf(sum / M + 512.0f * EPS) + logf(M) + cvs[b];
            if (out_size >= 65664)      out[65536 + team * 8 + b] = ll;
            else if (out_size == 128)   out[team * 8 + b] = ll;
        }
    }
}

// ---------------------------------------------------------------------------
extern "C" void kernel_launch(void* const* d_in, const int* in_sizes, int n_in,
                              void* d_out, int out_size) {
    const float* x = nullptr; const float* A = nullptr; const float* Bm = nullptr;
    for (int i = 0; i < n_in; ++i) {
        if (in_sizes[i] == 128 * T_LEN * 64)      x  = (const float*)d_in[i];
        else if (in_sizes[i] == 512 * 512)        A  = (const float*)d_in[i];
        else if (in_sizes[i] == 64 * 512)         Bm = (const float*)d_in[i];
    }
    if (!x)  x  = (const float*)d_in[0];
    if (!A)  A  = (const float*)d_in[1];
    if (!Bm) Bm = (const float*)d_in[2];

    cudaFuncSetAttribute(hmm_kernel,
                         cudaFuncAttributeMaxDynamicSharedMemorySize,
                         SMEM_BYTES);

    sym_kernel<<<(128 * T_LEN) / 8, 256>>>(x);
    hmm_kernel<<<128, 1024, SMEM_BYTES>>>(A, Bm, (float*)d_out, out_size);
}

// round 11
// speedup vs baseline: 1.5257x; 1.5257x over previous
#include <cuda_runtime.h>
#include <cstdint>

// ============================================================================
// CgpHmmCell: HMM forward scan. B=128, T=8192, S=512, M=64.
//
// Linear-domain rescaled recurrence (exactly the reference math):
//   F_0[b][s] = (s==0) ? E_0[b][0]+eps : 0 ;  C_0 = 0
//   step t:    M = max_s F_{t-1}[b][s] ;  C += log(M)  (Kahan)
//              y[b][j]   = sum_s F_{t-1}[b][s] * A[s][j]
//              F_t[b][j] = (E_t[b][j]+eps) * (y * (1/M) + eps)
//   alpha_T = log(F_T) + C ;  loglik = log(sum F_T/M_T + S*eps) + log(M_T) + C
//
// 16 teams x 8-CTA clusters, 512 threads/CTA (round-2 proven compute core).
// Exchange via st.async + parity mbarriers (NO per-step cluster.sync):
// each CTA waits only for its own incoming tx; skew absorbed; no L1 flush.
// ============================================================================

#define T_LEN 8192
#define EPS   1e-16f

typedef unsigned long long ull;

// word-offset smem map
#define FSTR      514                  // F batch stride (round-2 bank padding)
#define FBUFW     4112                 // 8 * FSTR
#define OFF_FB    32768                // fb[2][8][FSTR]
#define OFF_PART  40992                // part[32][512]
#define OFF_MAXB  57376                // maxb[2][8 b][16 src]
#define OFF_CV    57632                // cvs[8]
#define OFF_MBAR  57640                // 2 x u64 mbarrier (full[0], full[1])
#define SMEM_WORDS 57648
#define SMEM_BYTES (SMEM_WORDS * 4)    // 230592 <= 232448

// incoming per step: 8 srcs x (8b x 64j x 4B + 16 x 4B) = 8 x 2112
#define TX_BYTES  16896

__device__ unsigned char g_sym[128 * T_LEN];

// ---------------------------------------------------------------------------
__global__ void sym_kernel(const float* __restrict__ x) {
    int gw   = (blockIdx.x * blockDim.x + threadIdx.x) >> 5;
    int lane = threadIdx.x & 31;
    if (gw >= 128 * T_LEN) return;
    const float* p = x + (size_t)gw * 64;
    unsigned m1 = __ballot_sync(0xffffffffu, p[lane] > 0.5f);
    unsigned m2 = __ballot_sync(0xffffffffu, p[lane + 32] > 0.5f);
    if (lane == 0)
        g_sym[gw] = (unsigned char)(m1 ? (__ffs(m1) - 1) : (31 + __ffs(m2)));
}

// ---------------------------------------------------------------------------
__device__ __forceinline__ uint32_t smem_u32(const void* p) {
    uint32_t a;
    asm("{ .reg .u64 t; cvta.to.shared.u64 t, %1; cvt.u32.u64 %0, t; }"
        : "=r"(a) : "l"(p));
    return a;
}
__device__ __forceinline__ uint32_t mapa_u32(uint32_t a, uint32_t r) {
    uint32_t o;
    asm("mapa.shared::cluster.u32 %0, %1, %2;" : "=r"(o) : "r"(a), "r"(r));
    return o;
}
__device__ __forceinline__ void mb_init(uint32_t a, uint32_t cnt) {
    asm volatile("mbarrier.init.shared.b64 [%0], %1;" :: "r"(a), "r"(cnt) : "memory");
}
__device__ __forceinline__ void mb_expect(uint32_t a, uint32_t bytes) {
    asm volatile("mbarrier.arrive.expect_tx.shared.b64 _, [%0], %1;"
                 :: "r"(a), "r"(bytes) : "memory");
}
__device__ __forceinline__ void mb_wait(uint32_t a, uint32_t parity) {
    asm volatile(
        "{\n\t.reg .pred P;\n\t"
        "WL_%=:\n\t"
        "mbarrier.try_wait.parity.acquire.cta.shared::cta.b64 P, [%0], %1, 0x989680;\n\t"
        "@P bra.uni WD_%=;\n\t"
        "bra.uni WL_%=;\n\t"
        "WD_%=:\n\t}"
        :: "r"(a), "r"(parity) : "memory");
}
__device__ __forceinline__ void sta_b64(uint32_t dst, ull v, uint32_t mbar) {
    asm volatile(
        "st.async.shared::cluster.mbarrier::complete_tx::bytes.b64 [%0], %1, [%2];"
        :: "r"(dst), "l"(v), "r"(mbar) : "memory");
}
__device__ __forceinline__ void sta_b32(uint32_t dst, uint32_t v, uint32_t mbar) {
    asm volatile(
        "st.async.shared::cluster.mbarrier::complete_tx::bytes.b32 [%0], %1, [%2];"
        :: "r"(dst), "r"(v), "r"(mbar) : "memory");
}
__device__ __forceinline__ void cluster_arrive() {
    asm volatile("barrier.cluster.arrive.aligned;" ::: "memory");
}
__device__ __forceinline__ void cluster_wait() {
    asm volatile("barrier.cluster.wait.aligned;" ::: "memory");
}
#define FMA2(d, a, b) \
    asm("fma.rn.f32x2 %0, %1, %2, %0;" : "+l"(d) : "l"(a), "l"(b))
#define DUP2(d, f) \
    asm("mov.b64 %0, {%1, %1};" : "=l"(d) : "f"(f))

// ---------------------------------------------------------------------------
__global__ void __launch_bounds__(512, 1) __cluster_dims__(8, 1, 1)
hmm_kernel(const float* __restrict__ A, const float* __restrict__ Bm,
           float* __restrict__ out, int out_size) {
    extern __shared__ float sm[];
    float* fb   = sm + OFF_FB;
    float* part = sm + OFF_PART;
    float* maxb = sm + OFF_MAXB;
    float* cvs  = sm + OFF_CV;

    int tid = threadIdx.x;
    uint32_t rank;
    asm("mov.u32 %0, %%cluster_ctarank;" : "=r"(rank));
    int team = blockIdx.x >> 3;
    int wid = tid >> 5, lane = tid & 31;

    uint32_t base = smem_u32(sm);
    uint32_t mb_local = base + OFF_MBAR * 4;

    // ---- load A slice row-major: As[s][64] ----
    for (int i = tid; i < 512 * 64; i += 512) {
        int s = i >> 6, j = i & 63;
        sm[i] = A[s * 512 + (rank << 6) + j];
    }
    // ---- init fb (both parities), maxb, mbarriers ----
    for (int i = tid; i < 2 * FBUFW; i += 512) fb[i] = 0.0f;
    for (int i = tid; i < 256; i += 512) maxb[i] = 0.0f;
    if (tid == 0) { mb_init(mb_local, 1); mb_init(mb_local + 8, 1); }
    __syncthreads();
    if (tid < 8) {
        int bglob = team * 8 + tid;
        float e0 = Bm[(int)g_sym[(size_t)bglob * T_LEN] * 512] + EPS;
        fb[tid * FSTR] = e0;               // F0[b][0], parity 0
        maxb[tid * 16] = e0;               // parity0, b=tid, src0
    }
    __syncthreads();
    cluster_arrive(); cluster_wait();      // one-time: peers seeded + mbar init

    // peer smem bases
    uint32_t pb[8];
    #pragma unroll
    for (int c = 0; c < 8; ++c) pb[c] = mapa_u32(base, c);

    // finalize identity: one (b, j) per thread
    int ob = tid >> 6, oj = tid & 63;
    int bglob = team * 8 + ob;
    const unsigned char* symrow = g_sym + (size_t)bglob * T_LEN;
    const float* Bcol = Bm + (rank << 6) + oj;
    uint32_t fpush_rel = (uint32_t)(OFF_FB + ob * FSTR + (rank << 6) + oj) << 2;
    uint32_t mpush_rel = (uint32_t)(OFF_MAXB + ob * 16 + (rank << 1) + (wid & 1)) << 2;

    // MAC identity (round-2): jg j-group, bg batch-half, kg s-chunk
    int jg = tid & 7, bg = (tid >> 3) & 1, kg = tid >> 4;

    float Cv = 0.0f, Ck = 0.0f;            // Kahan C (oj==0 threads)
    int ph0 = 0, ph1 = 0;                  // mbarrier phase parities

    for (int t = 1; t < T_LEN; ++t) {
        int p = t & 1, rp = p ^ 1;

        // prime this step's incoming barrier (tx accumulates order-independently)
        if (tid == 0) mb_expect(mb_local + (p << 3), TX_BYTES);

        // wait for F_{t-1} + maxes (t=1 seeded locally, covered by cluster.sync)
        if (t > 1) {
            mb_wait(mb_local + (rp << 3), rp ? ph1 : ph0);
            if (rp) ph1 ^= 1; else ph0 ^= 1;
        }

        // E prefetch (L1 stays warm — no cluster.sync flush anymore)
        float e = Bcol[(int)symrow[t] * 512];

        // ---- MAC (round-2 core): acc[4 batches][4 f32x2] over 16 s ----
        const float* Frd  = fb + (rp ? FBUFW : 0) + bg * (4 * FSTR) + (kg << 4);
        const float* Arow = sm + (kg << 10) + (jg << 2);
        ull acc0[4], acc1[4], acc2[4], acc3[4];
        #pragma unroll
        for (int bi = 0; bi < 4; ++bi) { acc0[bi]=0; acc1[bi]=0; acc2[bi]=0; acc3[bi]=0; }

        #pragma unroll
        for (int sp = 0; sp < 8; ++sp) {
            const float* ar = Arow + (sp << 7);           // rows 2sp, 2sp+1
            ulonglong2 A0  = *(const ulonglong2*)(ar);
            ulonglong2 A0h = *(const ulonglong2*)(ar + 32);
            ulonglong2 A1  = *(const ulonglong2*)(ar + 64);
            ulonglong2 A1h = *(const ulonglong2*)(ar + 96);
            #pragma unroll
            for (int bi = 0; bi < 4; ++bi) {
                float2 f2 = *(const float2*)(Frd + bi * FSTR + (sp << 1));
                ull flo, fhi;
                DUP2(flo, f2.x);
                DUP2(fhi, f2.y);
                FMA2(acc0[bi], A0.x,  flo);
                FMA2(acc1[bi], A0.y,  flo);
                FMA2(acc2[bi], A0h.x, flo);
                FMA2(acc3[bi], A0h.y, flo);
                FMA2(acc0[bi], A1.x,  fhi);
                FMA2(acc1[bi], A1.y,  fhi);
                FMA2(acc2[bi], A1h.x, fhi);
                FMA2(acc3[bi], A1h.y, fhi);
            }
        }

        // ---- stage partials: part[kg][(bg*4+bi)*64 + jcol] ----
        float* prow = part + (kg << 9) + (bg << 8) + (jg << 2);
        #pragma unroll
        for (int bi = 0; bi < 4; ++bi) {
            *(ulonglong2*)(prow + bi * 64)      = make_ulonglong2(acc0[bi], acc1[bi]);
            *(ulonglong2*)(prow + bi * 64 + 32) = make_ulonglong2(acc2[bi], acc3[bi]);
        }
        __syncthreads();

        // ---- reduce 32 partials ----
        float s0 = 0, s1 = 0, s2 = 0, s3 = 0;
        const float* pc = part + tid;
        #pragma unroll
        for (int k = 0; k < 32; k += 4) {
            s0 += pc[k * 512];        s1 += pc[(k + 1) * 512];
            s2 += pc[(k + 2) * 512];  s3 += pc[(k + 3) * 512];
        }
        float y = (s0 + s1) + (s2 + s3);

        // ---- per-thread invM (broadcast reads of maxb[rp][ob][0..15]) ----
        const float* mr = maxb + (rp << 7) + (ob << 4);
        float M = mr[0];
        #pragma unroll
        for (int c = 1; c < 16; ++c) M = fmaxf(M, mr[c]);
        float inv = 1.0f / M;

        // ---- Kahan C (oj==0 threads; logf off critical path) ----
        if (oj == 0) {
            float yv = logf(M) - Ck;
            float tt = Cv + yv;
            Ck = (tt - Cv) - yv;
            Cv = tt;
        }

        float fnew = (e + EPS) * (y * inv + EPS);

        // ---- push F pairs to all 8 CTAs (incl. self) via st.async ----
        float fhi_v = __shfl_down_sync(0xffffffffu, fnew, 1);
        if ((oj & 1) == 0) {
            ull pr;
            asm("mov.b64 %0, {%1, %2};" : "=l"(pr) : "f"(fnew), "f"(fhi_v));
            uint32_t rel = fpush_rel + ((uint32_t)(p * FBUFW) << 2);
            uint32_t mb_off = (uint32_t)(OFF_MBAR << 2) + (uint32_t)(p << 3);
            #pragma unroll
            for (int c = 0; c < 8; ++c)
                sta_b64(pb[c] + rel, pr, pb[c] + mb_off);
        }

        // ---- warp half-batch max -> push to all maxbufs ----
        float wm = fnew;
        #pragma unroll
        for (int o2 = 16; o2; o2 >>= 1)
            wm = fmaxf(wm, __shfl_xor_sync(0xffffffffu, wm, o2));
        if (lane == 0) {
            uint32_t rel = mpush_rel + ((uint32_t)(p << 7) << 2);
            uint32_t mb_off = (uint32_t)(OFF_MBAR << 2) + (uint32_t)(p << 3);
            uint32_t wv = __float_as_uint(wm);
            #pragma unroll
            for (int c = 0; c < 8; ++c)
                sta_b32(pb[c] + rel, wv, pb[c] + mb_off);
        }
        __syncthreads();   // protect 'part' against next step's staging
    }

    // ---- epilogue: wait final exchange (parity 1 barrier), then outputs ----
    mb_wait(mb_local + 8, ph1);
    if (oj == 0) cvs[ob] = Cv;
    __syncthreads();

    {
        float F = fb[FBUFW + ob * FSTR + (rank << 6) + oj];   // parity 1
        float alpha = logf(F) + cvs[ob];
        if (out_size >= 65536)
            out[(size_t)bglob * 512 + (rank << 6) + oj] = alpha;
    }

    if (rank == 0 && wid < 8) {
        int b = wid;
        const float* fr = fb + FBUFW + b * FSTR;
        float sum = 0.0f;
        for (int s = lane; s < 512; s += 32) sum += fr[s];
        #pragma unroll
        for (int o2 = 16; o2; o2 >>= 1)
            sum += __shfl_xor_sync(0xffffffffu, sum, o2);
        if (lane == 0) {
            const float* mr = maxb + 128 + (b << 4);          // parity 1
            float M = mr[0];
            #pragma unroll
            for (int c = 1; c < 16; ++c) M = fmaxf(M, mr[c]);
            float ll = logf(sum / M + 512.0f * EPS) + logf(M) + cvs[b];
            if (out_size >= 65664)      out[65536 + team * 8 + b] = ll;
            else if (out_size == 128)   out[team * 8 + b] = ll;
        }
    }
}

// ---------------------------------------------------------------------------
extern "C" void kernel_launch(void* const* d_in, const int* in_sizes, int n_in,
                              void* d_out, int out_size) {
    const float* x = nullptr; const float* A = nullptr; const float* Bm = nullptr;
    for (int i = 0; i < n_in; ++i) {
        if (in_sizes[i] == 128 * T_LEN * 64)      x  = (const float*)d_in[i];
        else if (in_sizes[i] == 512 * 512)        A  = (const float*)d_in[i];
        else if (in_sizes[i] == 64 * 512)         Bm = (const float*)d_in[i];
    }
    if (!x)  x  = (const float*)d_in[0];
    if (!A)  A  = (const float*)d_in[1];
    if (!Bm) Bm = (const float*)d_in[2];

    cudaFuncSetAttribute(hmm_kernel,
                         cudaFuncAttributeMaxDynamicSharedMemorySize,
                         SMEM_BYTES);

    sym_kernel<<<(128 * T_LEN) / 8, 256>>>(x);
    hmm_kernel<<<128, 512, SMEM_BYTES>>>(A, Bm, (float*)d_out, out_size);
}